// round 15
// baseline (speedup 1.0000x reference)
#include <cuda_runtime.h>
#include <cuda_bf16.h>
#include <math.h>
#include <stdint.h>

// Problem constants
#define BB   64      // batch
#define TT   128     // seq len
#define HH   512     // hidden
#define NSEQ 128     // B * S (2 segments batched)
#define RNN_BLOCKS 128

// ---------------- scratch (__device__ globals; no allocations) ----------------
__device__ __nv_bfloat16 g_Ah[(size_t)8192 * 1024]; // t_emb hi  [n][1024]
__device__ __nv_bfloat16 g_Al[(size_t)8192 * 1024]; // t_emb lo
__device__ __nv_bfloat16 g_Bh[(size_t)2048 * 1024]; // W_ih[:,512:1536] hi [r][1024]
__device__ __nv_bfloat16 g_Bl[(size_t)2048 * 1024]; // W_ih lo
__device__ float g_gin [(size_t)128 * 128 * 2048];  // [t2][seq][r] fused input gates (+biases)
__device__ __nv_bfloat16 g_hhh[(size_t)128 * 128 * 512]; // [t][seq][k] h history hi
__device__ __nv_bfloat16 g_hhl[(size_t)128 * 128 * 512]; // [t][seq][k] h history lo
__device__ __nv_bfloat16 g_h0h[128 * 512];          // [seq][k] init h hi
__device__ __nv_bfloat16 g_h0l[128 * 512];          // [seq][k] init h lo
__device__ float g_c   [512 * 128];                 // [k][seq] c init
__device__ float g_Mt  [2048 * 16];                 // per-gate-row: {M_e0[8], M_e1[6], cst0, cst1}
__device__ __align__(128) int g_flagA[4][32];       // per-seq-group arrival flags (1 cache line each)

__device__ __forceinline__ float sigf(float x) { return 1.0f / (1.0f + expf(-x)); }

__device__ __forceinline__ uint32_t smem_u32(const void* p) {
    uint32_t a;
    asm("{ .reg .u64 t; cvta.to.shared.u64 t, %1; cvt.u32.u64 %0, t; }" : "=r"(a) : "l"(p));
    return a;
}
__device__ __forceinline__ void ldsm4(uint32_t* r, uint32_t addr) {
    asm volatile("ldmatrix.sync.aligned.m8n8.x4.shared.b16 {%0,%1,%2,%3}, [%4];"
                 : "=r"(r[0]), "=r"(r[1]), "=r"(r[2]), "=r"(r[3]) : "r"(addr));
}
__device__ __forceinline__ void mma16816(float* c, const uint32_t* a, const uint32_t* b) {
    asm volatile("mma.sync.aligned.m16n8k16.row.col.f32.bf16.bf16.f32 "
                 "{%0,%1,%2,%3}, {%4,%5,%6,%7}, {%8,%9}, {%0,%1,%2,%3};"
                 : "+f"(c[0]), "+f"(c[1]), "+f"(c[2]), "+f"(c[3])
                 : "r"(a[0]), "r"(a[1]), "r"(a[2]), "r"(a[3]), "r"(b[0]), "r"(b[1]));
}
#define CP_ASYNC16(dst, src) \
    asm volatile("cp.async.cg.shared.global [%0], [%1], 16;" :: "r"(dst), "l"(src))

// ---------------- K0: fold W_is / biases; write g_Mt[r][16] ----------------
__global__ void k_prep(const float* __restrict__ Wis0, const float* __restrict__ bis0,
                       const float* __restrict__ Wis1, const float* __restrict__ bis1,
                       const float* __restrict__ Wih,  const float* __restrict__ bih,
                       const float* __restrict__ bhh) {
    int r   = blockIdx.x;          // gate row 0..2047
    int tid = threadIdx.x;         // 128
    float acc[16];
#pragma unroll
    for (int j = 0; j < 16; j++) acc[j] = 0.0f;
    const float* wr = Wih + (size_t)r * 1536;      // W_ih row r, cols 0..511
    for (int k = tid; k < 512; k += 128) {
        float w = wr[k];
#pragma unroll
        for (int j = 0; j < 8; j++) acc[j]     += Wis0[k * 8 + j] * w;
#pragma unroll
        for (int j = 0; j < 6; j++) acc[8 + j] += Wis1[k * 6 + j] * w;
        acc[14] += bis0[k] * w;
        acc[15] += bis1[k] * w;
    }
    __shared__ float red[16][128];
#pragma unroll
    for (int j = 0; j < 16; j++) red[j][tid] = acc[j];
    __syncthreads();
    for (int s = 64; s > 0; s >>= 1) {
        if (tid < s) {
#pragma unroll
            for (int j = 0; j < 16; j++) red[j][tid] += red[j][tid + s];
        }
        __syncthreads();
    }
    if (tid < 14) g_Mt[r * 16 + tid] = red[tid][0];
    if (tid == 14) g_Mt[r * 16 + 14] = red[14][0] + bih[r] + bhh[r];
    if (tid == 15) g_Mt[r * 16 + 15] = red[15][0] + bih[r] + bhh[r];
}

// ---------------- K1 merged: temb (blocks 0..8191) | cvtw (8192..10239) | init (10240..10367) ----------------
__global__ void k_pre(const float* __restrict__ x, const float* __restrict__ Wih,
                      const float* __restrict__ h0, const float* __restrict__ c0) {
    int bid = blockIdx.x;
    int tid = threadIdx.x;   // 256
    if (bid < 8192) {
        // timestep embeddings, bf16 hi/lo
        int n = bid;
        float tc = x[n * 16 + 0];
        float tp = x[n * 16 + 1];
        float f  = expf(-9.210340371976184f * (float)tid * (1.0f / 256.0f));
        float s, c;
        __nv_bfloat16* ah = g_Ah + (size_t)n * 1024;
        __nv_bfloat16* al = g_Al + (size_t)n * 1024;
        sincosf(tc * f, &s, &c);
        {
            __nv_bfloat16 h = __float2bfloat16(c);
            ah[tid] = h;        al[tid] = __float2bfloat16(c - __bfloat162float(h));
            h = __float2bfloat16(s);
            ah[256 + tid] = h;  al[256 + tid] = __float2bfloat16(s - __bfloat162float(h));
        }
        sincosf(tp * f, &s, &c);
        {
            __nv_bfloat16 h = __float2bfloat16(c);
            ah[512 + tid] = h;  al[512 + tid] = __float2bfloat16(c - __bfloat162float(h));
            h = __float2bfloat16(s);
            ah[768 + tid] = h;  al[768 + tid] = __float2bfloat16(s - __bfloat162float(h));
        }
    } else if (bid < 10240) {
        // convert W_ih[:,512:1536] to bf16 hi/lo
        int r = bid - 8192;
        for (int k = tid; k < 1024; k += 256) {
            float w = Wih[(size_t)r * 1536 + 512 + k];
            __nv_bfloat16 h = __float2bfloat16(w);
            g_Bh[(size_t)r * 1024 + k] = h;
            g_Bl[(size_t)r * 1024 + k] = __float2bfloat16(w - __bfloat162float(h));
        }
    } else {
        // init h (bf16 hi/lo, [seq][k]) and c (fp32 [k][seq]); reset barrier flags
        int idx = (bid - 10240) * 256 + tid;     // over 64*512
        if (idx < 128) g_flagA[idx >> 5][idx & 31] = 0;
        int b = idx >> 9, k = idx & 511;
        float hv = h0[b * 512 + k], cv = c0[b * 512 + k];
        __nv_bfloat16 hi = __float2bfloat16(hv);
        __nv_bfloat16 lo = __float2bfloat16(hv - __bfloat162float(hi));
        g_h0h[(size_t)b * 512 + k] = hi;  g_h0h[(size_t)(64 + b) * 512 + k] = hi;
        g_h0l[(size_t)b * 512 + k] = lo;  g_h0l[(size_t)(64 + b) * 512 + k] = lo;
        g_c[k * 128 + b] = cv;  g_c[k * 128 + 64 + b] = cv;
    }
}

// ---------------- K3: HMMA bf16 GEMM  gin = t_emb @ W_ih[:,512:1536].T (hi/lo split, 3 products) ----------------
// Grid (32, 64): M=128 (batch by), N=64 (bx). 8 warps (2m x 4n), warp tile 64x16.
// 3-stage cp.async pipeline; 2 blocks/SM.
#define MPITCH 40
#define MSTAGE 30720
#define MMA_SMEM (3 * MSTAGE)
__global__ __launch_bounds__(256, 2) void k_mma(const float* __restrict__ x) {
    extern __shared__ char dsm[];
    uint32_t sb = smem_u32(dsm);

    int tid = threadIdx.x;
    int warp = tid >> 5, lane = tid & 31;
    int warp_m = warp >> 2;           // 0..1
    int warp_n = warp & 3;            // 0..3
    int bx = blockIdx.x;              // n-tile 0..31 (64 gate rows each)
    int by = blockIdx.y;              // m-tile == batch b, 0..63

    const __nv_bfloat16* srcA_h = g_Ah + (size_t)by * 128 * 1024;
    const __nv_bfloat16* srcA_l = g_Al + (size_t)by * 128 * 1024;
    const __nv_bfloat16* srcB_h = g_Bh + (size_t)bx * 64 * 1024;
    const __nv_bfloat16* srcB_l = g_Bl + (size_t)bx * 64 * 1024;

    int la7 = lane & 7, lb = (lane >> 3) & 1, lc = lane >> 4;
    int arow = warp_m * 64 + la7 + lb * 8;
    int acol0 = lc * 8;
    int brow = warp_n * 16 + la7 + lc * 8;
    int bcol0 = lb * 8;

    // load addressing
    uint32_t a_off0 = (uint32_t)((tid >> 2) * 80 + (tid & 3) * 16);
    uint32_t a_off1 = a_off0 + 64 * 80;
    size_t a_g0 = (size_t)(tid >> 2) * 1024 + (tid & 3) * 8;
    size_t a_g1 = a_g0 + (size_t)64 * 1024;
    uint32_t b_off = a_off0;                      // rows 0..63
    size_t b_g = a_g0;

#define MISSUE(KC, ST) do {                                                    \
    uint32_t base = sb + (ST) * MSTAGE;                                        \
    size_t gc_ = (size_t)(KC);                                                 \
    CP_ASYNC16(base +         a_off0, srcA_h + a_g0 + gc_);                    \
    CP_ASYNC16(base + 10240 + a_off0, srcA_l + a_g0 + gc_);                    \
    CP_ASYNC16(base +         a_off1, srcA_h + a_g1 + gc_);                    \
    CP_ASYNC16(base + 10240 + a_off1, srcA_l + a_g1 + gc_);                    \
    CP_ASYNC16(base + 20480 + b_off, srcB_h + b_g + gc_);                      \
    CP_ASYNC16(base + 25600 + b_off, srcB_l + b_g + gc_);                      \
    asm volatile("cp.async.commit_group;");                                    \
} while (0)

    float acc[4][2][4];
#pragma unroll
    for (int i = 0; i < 4; i++)
#pragma unroll
        for (int j = 0; j < 2; j++)
#pragma unroll
            for (int q = 0; q < 4; q++) acc[i][j][q] = 0.0f;

    MISSUE(0, 0);
    MISSUE(32, 1);
    for (int kt = 0; kt < 32; kt++) {
        int st = kt % 3;
        if (kt < 30) {
            MISSUE((kt + 2) * 32, (kt + 2) % 3);
            asm volatile("cp.async.wait_group 2;");
        } else if (kt == 30) {
            asm volatile("cp.async.wait_group 1;");
        } else {
            asm volatile("cp.async.wait_group 0;");
        }
        __syncthreads();

        uint32_t uAh = sb + st * MSTAGE;
        uint32_t uAl = uAh + 10240;
        uint32_t uBh = uAh + 20480;
        uint32_t uBl = uAh + 25600;

#pragma unroll
        for (int ks = 0; ks < 2; ks++) {
            uint32_t ah[4][4], al[4][4], bh[2][2], bl[2][2];
            int acol = ks * 16 + acol0;
            int bcol = ks * 16 + bcol0;
#pragma unroll
            for (int mi = 0; mi < 4; mi++) {
                uint32_t off = (uint32_t)(((arow + mi * 16) * MPITCH + acol) * 2);
                ldsm4(ah[mi], uAh + off);
                ldsm4(al[mi], uAl + off);
            }
            {
                uint32_t off = (uint32_t)((brow * MPITCH + bcol) * 2);
                uint32_t r[4];
                ldsm4(r, uBh + off);
                bh[0][0] = r[0]; bh[0][1] = r[1]; bh[1][0] = r[2]; bh[1][1] = r[3];
                ldsm4(r, uBl + off);
                bl[0][0] = r[0]; bl[0][1] = r[1]; bl[1][0] = r[2]; bl[1][1] = r[3];
            }
#pragma unroll
            for (int mi = 0; mi < 4; mi++)
#pragma unroll
                for (int ni = 0; ni < 2; ni++) {
                    mma16816(acc[mi][ni], ah[mi], bh[ni]);
                    mma16816(acc[mi][ni], ah[mi], bl[ni]);
                    mma16816(acc[mi][ni], al[mi], bh[ni]);
                }
        }
        __syncthreads();
    }
#undef MISSUE

    int gr = lane >> 2, gc = (lane & 3) * 2;
#pragma unroll
    for (int mi = 0; mi < 4; mi++) {
#pragma unroll
        for (int half = 0; half < 2; half++) {
            int m = warp_m * 64 + mi * 16 + gr + half * 8;   // original timestep t
            int s2 = m >> 6;
            int t0 = 2 * (m & 63);
            int seq = s2 * 64 + by;
            const float* xr = x + ((size_t)(by * 128 + m)) * 16 + 2;
            float xs[14];
#pragma unroll
            for (int jj = 0; jj < 14; jj++) xs[jj] = xr[jj];
            float* g0 = g_gin + ((size_t)t0 * 128 + seq) * 2048 + bx * 64;
            float* g1 = g0 + (size_t)128 * 2048;
#pragma unroll
            for (int ni = 0; ni < 2; ni++) {
                int lcol = warp_n * 16 + ni * 8 + gc;
                int r = bx * 64 + lcol;
                float b0 = acc[mi][ni][half * 2 + 0];
                float b1 = acc[mi][ni][half * 2 + 1];
                float v0a, v1a, v0b, v1b;
                {
                    const float4* mt = (const float4*)(g_Mt + (size_t)r * 16);
                    float4 m0 = mt[0], m1 = mt[1], m2 = mt[2], m3 = mt[3];
                    v0a = b0 + m3.z + xs[0]*m0.x + xs[1]*m0.y + xs[2]*m0.z + xs[3]*m0.w
                               + xs[4]*m1.x + xs[5]*m1.y + xs[6]*m1.z + xs[7]*m1.w;
                    v1a = b0 + m3.w + xs[8]*m2.x + xs[9]*m2.y + xs[10]*m2.z + xs[11]*m2.w
                               + xs[12]*m3.x + xs[13]*m3.y;
                }
                {
                    const float4* mt = (const float4*)(g_Mt + (size_t)(r + 1) * 16);
                    float4 m0 = mt[0], m1 = mt[1], m2 = mt[2], m3 = mt[3];
                    v0b = b1 + m3.z + xs[0]*m0.x + xs[1]*m0.y + xs[2]*m0.z + xs[3]*m0.w
                               + xs[4]*m1.x + xs[5]*m1.y + xs[6]*m1.z + xs[7]*m1.w;
                    v1b = b1 + m3.w + xs[8]*m2.x + xs[9]*m2.y + xs[10]*m2.z + xs[11]*m2.w
                               + xs[12]*m3.x + xs[13]*m3.y;
                }
                *(float2*)(g0 + lcol) = make_float2(v0a, v0b);
                *(float2*)(g1 + lcol) = make_float2(v1a, v1b);
            }
        }
    }
}

// ---------------- K4: persistent HMMA LSTM recurrence ----------------
// 128 blocks = 32 unit-groups x 4 seq-groups. Block owns 16 units (64 gate rows,
// a = g*16+u) x 32 seqs. Only blocks sharing a seq-group communicate ->
// 4 independent atomic-free flag barriers (one 128B line each; 32 threads poll
// one flag word apiece).
#define AP 520                          // A smem pitch (bf16 elems)
#define BP 136                          // B smem pitch (bf16 elems)
#define GP 36                           // gsm pitch (floats)
#define SA_H 0
#define SA_L 66560
#define SB_H0 133120
#define SB_L0 141824
#define SB_H1 150528
#define SB_L1 159232
#define SGM   167936
#define RNN_SMEM 177152

__global__ __launch_bounds__(256) void k_rnn(const float* __restrict__ Whh) {
    extern __shared__ char sm[];
    uint32_t sb = smem_u32(sm);
    __nv_bfloat16* sAh = (__nv_bfloat16*)(sm + SA_H);
    __nv_bfloat16* sAl = (__nv_bfloat16*)(sm + SA_L);
    float* gsm = (float*)(sm + SGM);

    int tid = threadIdx.x, warp = tid >> 5, lane = tid & 31;
    int ug = blockIdx.x >> 2, sg = blockIdx.x & 3;
    int j16 = ug * 16;                 // unit base
    int s32 = sg * 32;                 // seq base
    int wm = warp & 3, wn = warp >> 2; // warp tile coords

    // Stage A: 64 W_hh rows (a = g*16+u -> global row g*512 + j16 + u) bf16 hi/lo, once.
    for (int i = tid; i < 64 * 512; i += 256) {
        int a = i >> 9, k = i & 511;
        float w = Whh[(size_t)((a >> 4) * 512 + j16 + (a & 15)) * 512 + k];
        __nv_bfloat16 hi = __float2bfloat16(w);
        sAh[a * AP + k] = hi;
        sAl[a * AP + k] = __float2bfloat16(w - __bfloat162float(hi));
    }

    // Cell-state ownership: thread -> (units j16+u0, j16+u0+1; seq gseq)
    int sl = tid & 31;
    int u0 = (tid >> 5) * 2;           // 0..14
    int gseq = s32 + sl;
    float cc[2];
    cc[0] = g_c[(j16 + u0) * 128 + gseq];
    cc[1] = g_c[(j16 + u0 + 1) * 128 + gseq];
    __syncthreads();

    int la7 = lane & 7, lb2 = (lane >> 3) & 1, lc2 = lane >> 4;
    int arow = wm * 16 + la7 + lb2 * 8;
    int acol0 = lc2 * 8;
    int brow = wn * 16 + la7 + lc2 * 8;
    int bcol0 = lb2 * 8;
    uint32_t bufH[2] = {sb + SB_H0, sb + SB_H1};
    uint32_t bufL[2] = {sb + SB_L0, sb + SB_L1};

#define ISSUE_CHUNK(KC, BUF) do {                                              \
    _Pragma("unroll")                                                          \
    for (int j = 0; j < 2; j++) {                                              \
        int gidx = tid * 2 + j;                                                \
        int row = gidx >> 4, seg = gidx & 15;                                  \
        uint32_t so = (uint32_t)(row * (BP * 2) + seg * 16);                   \
        size_t go_ = (size_t)(s32 + row) * 512 + (size_t)(KC) * 128 + seg * 8; \
        CP_ASYNC16(bufH[BUF] + so, srcH + go_);                                \
        CP_ASYNC16(bufL[BUF] + so, srcL + go_);                                \
    }                                                                          \
    asm volatile("cp.async.commit_group;");                                    \
} while (0)

    for (int t = 0; t < 128; t++) {
        const __nv_bfloat16* srcH = (t == 0) ? g_h0h : (g_hhh + (size_t)(t - 1) * 65536);
        const __nv_bfloat16* srcL = (t == 0) ? g_h0l : (g_hhl + (size_t)(t - 1) * 65536);

        ISSUE_CHUNK(0, 0);

        // Hoisted gin loads: independent of h, overlap their latency with the MMA loop.
        const float* ginb = g_gin + ((size_t)t * 128 + gseq) * 2048 + j16 + u0;
        float2 xi = *(const float2*)(ginb);
        float2 xf = *(const float2*)(ginb + 512);
        float2 xg = *(const float2*)(ginb + 1024);
        float2 xo = *(const float2*)(ginb + 1536);

        float acc0[4] = {0, 0, 0, 0}, acc1[4] = {0, 0, 0, 0};

        for (int kc4 = 0; kc4 < 4; kc4++) {
            int cb = kc4 & 1;
            if (kc4 < 3) {
                ISSUE_CHUNK(kc4 + 1, cb ^ 1);
                asm volatile("cp.async.wait_group 1;");
            } else {
                asm volatile("cp.async.wait_group 0;");
            }
            __syncthreads();
#pragma unroll
            for (int ks = 0; ks < 8; ks++) {
                int acol = kc4 * 128 + ks * 16 + acol0;
                uint32_t aoff = (uint32_t)((arow * AP + acol) * 2);
                uint32_t ah[4], al[4];
                ldsm4(ah, sb + SA_H + aoff);
                ldsm4(al, sb + SA_L + aoff);
                uint32_t boff = (uint32_t)((brow * BP + bcol0 + ks * 16) * 2);
                uint32_t r[4], bh0[2], bh1[2], bl0[2], bl1[2];
                ldsm4(r, bufH[cb] + boff);
                bh0[0] = r[0]; bh0[1] = r[1]; bh1[0] = r[2]; bh1[1] = r[3];
                ldsm4(r, bufL[cb] + boff);
                bl0[0] = r[0]; bl0[1] = r[1]; bl1[0] = r[2]; bl1[1] = r[3];
                mma16816(acc0, ah, bh0);
                mma16816(acc0, ah, bl0);
                mma16816(acc0, al, bh0);
                mma16816(acc1, ah, bh1);
                mma16816(acc1, ah, bl1);
                mma16816(acc1, al, bh1);
            }
            __syncthreads();
        }

        // Store gate sums to gsm[a][sl]: rows wm*16+{gr,gr+8}, cols wn*16 + gc (+8)
        int gr = lane >> 2, gc = (lane & 3) * 2;
        *(float2*)&gsm[(wm * 16 + gr) * GP + wn * 16 + gc]         = make_float2(acc0[0], acc0[1]);
        *(float2*)&gsm[(wm * 16 + gr + 8) * GP + wn * 16 + gc]     = make_float2(acc0[2], acc0[3]);
        *(float2*)&gsm[(wm * 16 + gr) * GP + wn * 16 + 8 + gc]     = make_float2(acc1[0], acc1[1]);
        *(float2*)&gsm[(wm * 16 + gr + 8) * GP + wn * 16 + 8 + gc] = make_float2(acc1[2], acc1[3]);
        __syncthreads();

        // Update phase: thread handles (seq=gseq, units u0, u0+1); gate g row = g*16+u
        float xiv[2] = {xi.x, xi.y};
        float xfv[2] = {xf.x, xf.y};
        float xgv[2] = {xg.x, xg.y};
        float xov[2] = {xo.x, xo.y};
        float hn[2];
#pragma unroll
        for (int q = 0; q < 2; q++) {
            int u = u0 + q;
            float gi = gsm[u * GP + sl]        + xiv[q];
            float gf = gsm[(16 + u) * GP + sl] + xfv[q];
            float gg = gsm[(32 + u) * GP + sl] + xgv[q];
            float go = gsm[(48 + u) * GP + sl] + xov[q];
            cc[q] = sigf(gf) * cc[q] + sigf(gi) * tanhf(gg);
            hn[q] = sigf(go) * tanhf(cc[q]);
        }
        __align__(4) __nv_bfloat16 hhv[2], hlv[2];
#pragma unroll
        for (int q = 0; q < 2; q++) {
            __nv_bfloat16 hi = __float2bfloat16(hn[q]);
            hhv[q] = hi;
            hlv[q] = __float2bfloat16(hn[q] - __bfloat162float(hi));
        }
        size_t hb = ((size_t)t * 128 + gseq) * 512 + j16 + u0;
        *(uint32_t*)(g_hhh + hb) = *(uint32_t*)hhv;
        *(uint32_t*)(g_hhl + hb) = *(uint32_t*)hlv;

        if (t < 127) {
            __syncthreads();                          // all h[t] stores of this block issued
            if (tid == 0) {
                __threadfence();                      // release: publish h[t]
                *(volatile int*)&g_flagA[sg][ug] = t + 1;
            }
            if (tid < 32) {                           // poll the 32 same-sg flags (one 128B line)
                volatile int* f = &g_flagA[sg][tid];
                while (*f <= t) { }
                __threadfence();                      // acquire
            }
            __syncthreads();                          // release whole block
        }
    }
#undef ISSUE_CHUNK
}

// ---------------- K5: gather h at lengths-1 (hi+lo), output linear + sigmoid ----------------
__global__ void k_out(const float* __restrict__ Wo, const float* __restrict__ bo,
                      const int* __restrict__ lengths, float* __restrict__ out) {
    int b = blockIdx.x, o = blockIdx.y;
    int tid = threadIdx.x;             // 128
    int t = lengths[b] - 1;
    const __nv_bfloat16* ph = g_hhh + (size_t)t * 65536;
    const __nv_bfloat16* pl = g_hhl + (size_t)t * 65536;
    float acc = 0.0f;
    for (int k = tid; k < 512; k += 128) {
        float h0v = __bfloat162float(ph[(size_t)b * 512 + k])
                  + __bfloat162float(pl[(size_t)b * 512 + k]);
        float h1v = __bfloat162float(ph[(size_t)(64 + b) * 512 + k])
                  + __bfloat162float(pl[(size_t)(64 + b) * 512 + k]);
        acc += Wo[o * 1024 + k] * h0v + Wo[o * 1024 + 512 + k] * h1v;
    }
    __shared__ float red[128];
    red[tid] = acc;
    __syncthreads();
    for (int s = 64; s > 0; s >>= 1) {
        if (tid < s) red[tid] += red[tid + s];
        __syncthreads();
    }
    if (tid == 0) out[b * 14 + o] = 1.0f / (1.0f + expf(-(red[0] + bo[o])));
}

// ---------------- launch ----------------
extern "C" void kernel_launch(void* const* d_in, const int* in_sizes, int n_in,
                              void* d_out, int out_size) {
    const float* x     = (const float*)d_in[0];
    const int*   len   = (const int*)  d_in[1];
    const float* h0    = (const float*)d_in[2];
    const float* c0    = (const float*)d_in[3];
    const float* Wis0  = (const float*)d_in[4];
    const float* bis0  = (const float*)d_in[5];
    const float* Wis1  = (const float*)d_in[6];
    const float* bis1  = (const float*)d_in[7];
    const float* Wih   = (const float*)d_in[8];
    const float* Whh   = (const float*)d_in[9];
    const float* bih   = (const float*)d_in[10];
    const float* bhh   = (const float*)d_in[11];
    const float* Wo    = (const float*)d_in[12];
    const float* bo    = (const float*)d_in[13];
    float* out = (float*)d_out;

    cudaFuncSetAttribute(k_rnn, cudaFuncAttributeMaxDynamicSharedMemorySize, RNN_SMEM);
    cudaFuncSetAttribute(k_mma, cudaFuncAttributeMaxDynamicSharedMemorySize, MMA_SMEM);

    k_prep<<<2048, 128>>>(Wis0, bis0, Wis1, bis1, Wih, bih, bhh);
    k_pre<<<10368, 256>>>(x, Wih, h0, c0);
    k_mma<<<dim3(32, 64), 256, MMA_SMEM>>>(x);
    k_rnn<<<RNN_BLOCKS, 256, RNN_SMEM>>>(Whh);
    k_out<<<dim3(64, 14), 128>>>(Wo, bo, len, out);
}